// round 14
// baseline (speedup 1.0000x reference)
#include <cuda_runtime.h>
#include <cuda_fp16.h>
#include <cstdint>

#define N_NODES 50000
#define N_EDGES 800000
#define D_IN    256
#define D_HID   256
#define D_OUT   128

#define SCAN_B   1024
#define SCAN_NB  ((N_NODES + SCAN_B - 1) / SCAN_B)   // 49

// ---- scratch (no allocations allowed) ----
__device__ __half g_xf [N_NODES * D_IN];    // fp16(x)
__device__ __half g_m1 [N_NODES * D_IN];    // fp16(mean1)
__device__ __half g_hf [N_NODES * D_HID];   // fp16(h)
__device__ float  g_hp [N_NODES * D_HID];   // h_part = x@W1r + b1 (fp32)
__device__ __half g_w1 [D_HID * 2 * D_IN];  // B1^T: [256 n][512 k]
__device__ __half g_w2 [2 * D_OUT * D_HID]; // B2^T: [256 n][256 k]
__device__ __half g_y2f[N_NODES * D_OUT];   // fp16(h @ W2_l)
__device__ float g_z2[N_NODES * D_OUT];     // h @ W2_r + b2
__device__ int   g_deg[N_NODES];
__device__ int   g_rowstart[N_NODES + 1];
__device__ int   g_cursor[N_NODES];
__device__ int   g_csr[N_EDGES];
__device__ int   g_bsum[SCAN_NB];
__device__ int   g_boff[SCAN_NB];

__device__ __forceinline__ int clampi(int v) {
    return min(max(v, 0), N_NODES - 1);
}

__device__ __forceinline__ uint32_t hpack(__half a, __half b) {
    union { __half2 v; uint32_t u; } t;
    t.v.x = a; t.v.y = b;
    return t.u;
}

// ---- per-launch reset ----
__global__ void zero_deg_kernel() {
    int i = blockIdx.x * blockDim.x + threadIdx.x;
    if (i < N_NODES) g_deg[i] = 0;
}

// ---- prep: convert x + transposed fp16 weights (side stream) ----
__global__ void prep_kernel(const float* __restrict__ x,
                            const float* __restrict__ W1l,
                            const float* __restrict__ W1r,
                            const float* __restrict__ W2l,
                            const float* __restrict__ W2r) {
    int idx = blockIdx.x * blockDim.x + threadIdx.x;
    const int nx = N_NODES * D_IN / 4;
    if (idx < nx) {
        float4 v = ((const float4*)x)[idx];
        ((uint2*)g_xf)[idx] = make_uint2(
            hpack(__float2half(v.x), __float2half(v.y)),
            hpack(__float2half(v.z), __float2half(v.w)));
    }
    const int n1 = D_HID * 2 * D_IN;       // 131072
    const int n2 = 2 * D_OUT * D_HID;      // 65536
    if (idx < n1) {
        int n = idx >> 9, k = idx & 511;
        float v = (k < 256) ? W1l[k * D_HID + n] : W1r[(k - 256) * D_HID + n];
        g_w1[idx] = __float2half(v);
    }
    if (idx < n2) {
        int n = idx >> 8, k = idx & 255;
        float v = (n < 128) ? W2l[k * D_OUT + n] : W2r[k * D_OUT + (n - 128)];
        g_w2[idx] = __float2half(v);
    }
}

// ---- CSR build ----
__global__ void degree_kernel(const int* __restrict__ ei) {
    int i = blockIdx.x * blockDim.x + threadIdx.x;
    if (i >= N_EDGES / 4) return;
    int4 d = ((const int4*)(ei + N_EDGES))[i];
    atomicAdd(&g_deg[clampi(d.x)], 1);
    atomicAdd(&g_deg[clampi(d.y)], 1);
    atomicAdd(&g_deg[clampi(d.z)], 1);
    atomicAdd(&g_deg[clampi(d.w)], 1);
}

__global__ void scan_p1_kernel() {
    __shared__ int sh[SCAN_B];
    int t = threadIdx.x;
    int i = blockIdx.x * SCAN_B + t;
    int d = (i < N_NODES) ? g_deg[i] : 0;
    sh[t] = d;
    __syncthreads();
#pragma unroll
    for (int off = 1; off < SCAN_B; off <<= 1) {
        int v = (t >= off) ? sh[t - off] : 0;
        __syncthreads();
        sh[t] += v;
        __syncthreads();
    }
    if (i < N_NODES) g_cursor[i] = sh[t];       // inclusive prefix (local)
    if (t == SCAN_B - 1) g_bsum[blockIdx.x] = sh[t];
}

__global__ void scan_p2_kernel() {
    __shared__ int sh[64];
    int t = threadIdx.x;
    sh[t] = (t < SCAN_NB) ? g_bsum[t] : 0;
    __syncthreads();
#pragma unroll
    for (int off = 1; off < 64; off <<= 1) {
        int v = (t >= off) ? sh[t - off] : 0;
        __syncthreads();
        sh[t] += v;
        __syncthreads();
    }
    if (t < SCAN_NB) g_boff[t] = (t == 0) ? 0 : sh[t - 1];
    if (t == 0) g_rowstart[N_NODES] = sh[SCAN_NB - 1];
}

__global__ void scan_p3_kernel() {
    int i = blockIdx.x * SCAN_B + threadIdx.x;
    if (i >= N_NODES) return;
    int ex = g_cursor[i] - g_deg[i] + g_boff[blockIdx.x];
    g_rowstart[i] = ex;
    g_cursor[i] = ex;
}

__global__ void fill_kernel(const int* __restrict__ ei) {
    int i = blockIdx.x * blockDim.x + threadIdx.x;
    if (i >= N_EDGES / 4) return;
    int4 d = ((const int4*)(ei + N_EDGES))[i];
    int4 s = ((const int4*)ei)[i];
    int slot;
    slot = atomicAdd(&g_cursor[clampi(d.x)], 1); g_csr[slot] = clampi(s.x);
    slot = atomicAdd(&g_cursor[clampi(d.y)], 1); g_csr[slot] = clampi(s.y);
    slot = atomicAdd(&g_cursor[clampi(d.z)], 1); g_csr[slot] = clampi(s.z);
    slot = atomicAdd(&g_cursor[clampi(d.w)], 1); g_csr[slot] = clampi(s.w);
}

// ---- gather1: mean of fp16 x over in-neighbors -> fp16 (warp per node) ----
__device__ __forceinline__ void acc_row16(float* acc, const uint4& p) {
    float2 f0 = __half22float2(*(const __half2*)&p.x);
    float2 f1 = __half22float2(*(const __half2*)&p.y);
    float2 f2 = __half22float2(*(const __half2*)&p.z);
    float2 f3 = __half22float2(*(const __half2*)&p.w);
    acc[0] += f0.x; acc[1] += f0.y; acc[2] += f1.x; acc[3] += f1.y;
    acc[4] += f2.x; acc[5] += f2.y; acc[6] += f3.x; acc[7] += f3.y;
}

__global__ void gather1_kernel() {
    int node = (int)((blockIdx.x * (long)blockDim.x + threadIdx.x) >> 5);
    int lane = threadIdx.x & 31;
    if (node >= N_NODES) return;
    int s = g_rowstart[node], e = g_rowstart[node + 1];
    float acc[8];
#pragma unroll
    for (int j = 0; j < 8; j++) acc[j] = 0.f;
    int i = s;
    for (; i + 8 <= e; i += 8) {
        uint4 p[8];
#pragma unroll
        for (int u = 0; u < 8; u++)
            p[u] = ((const uint4*)(g_xf + (long)g_csr[i + u] * D_IN))[lane];
#pragma unroll
        for (int u = 0; u < 8; u++) acc_row16(acc, p[u]);
    }
    for (; i + 4 <= e; i += 4) {
        uint4 p[4];
#pragma unroll
        for (int u = 0; u < 4; u++)
            p[u] = ((const uint4*)(g_xf + (long)g_csr[i + u] * D_IN))[lane];
#pragma unroll
        for (int u = 0; u < 4; u++) acc_row16(acc, p[u]);
    }
    for (; i < e; i++) {
        uint4 p = ((const uint4*)(g_xf + (long)g_csr[i] * D_IN))[lane];
        acc_row16(acc, p);
    }
    float r = 1.0f / fmaxf((float)(e - s), 1.0f);
    uint4 p = make_uint4(
        hpack(__float2half(acc[0] * r), __float2half(acc[1] * r)),
        hpack(__float2half(acc[2] * r), __float2half(acc[3] * r)),
        hpack(__float2half(acc[4] * r), __float2half(acc[5] * r)),
        hpack(__float2half(acc[6] * r), __float2half(acc[7] * r)));
    ((uint4*)(g_m1 + (long)node * D_IN))[lane] = p;
}

// ======================================================================
// fp16 single-pass tensor GEMM machinery. Block 128x128, BK=32, 256 thr.
// 4-stage cp.async pipeline, ONE __syncthreads per iteration.
// ======================================================================
#define GBM 128
#define GBN 128
#define GBK 32
#define SPAD 40
#define NSTAGE 4

struct GemmSmem {
    __half A[GBM][SPAD];
    __half B[GBN][SPAD];
};
#define GEMM_SMEM_BYTES (NSTAGE * sizeof(GemmSmem))

__device__ __forceinline__ void cpa16(uint32_t dst, const void* src, int srcsize) {
    asm volatile("cp.async.cg.shared.global [%0], [%1], 16, %2;"
                 :: "r"(dst), "l"(src), "r"(srcsize));
}

__device__ __forceinline__ void ldsm_x4(uint32_t& r0, uint32_t& r1,
                                        uint32_t& r2, uint32_t& r3, uint32_t addr) {
    asm volatile("ldmatrix.sync.aligned.m8n8.x4.shared.b16 {%0,%1,%2,%3}, [%4];"
                 : "=r"(r0), "=r"(r1), "=r"(r2), "=r"(r3) : "r"(addr));
}

__device__ __forceinline__ void mma_fp16(float* d, const uint32_t* a,
                                         uint32_t b0, uint32_t b1) {
    asm volatile(
        "mma.sync.aligned.m16n8k16.row.col.f32.f16.f16.f32 "
        "{%0,%1,%2,%3}, {%4,%5,%6,%7}, {%8,%9}, {%0,%1,%2,%3};"
        : "+f"(d[0]), "+f"(d[1]), "+f"(d[2]), "+f"(d[3])
        : "r"(a[0]), "r"(a[1]), "r"(a[2]), "r"(a[3]), "r"(b0), "r"(b1));
}

__device__ __forceinline__ void pipe_wait(int c, int NC) {
    if (c < NC - 2)       asm volatile("cp.async.wait_group 2;");
    else if (c == NC - 2) asm volatile("cp.async.wait_group 1;");
    else                  asm volatile("cp.async.wait_group 0;");
}

__device__ __forceinline__ void load_chunk(GemmSmem* sm,
        const __half* A, int row0, int ka, int asr,
        const __half* B, int coln0, int kb, int bsr) {
    uint32_t bA = (uint32_t)__cvta_generic_to_shared(&sm->A[0][0]);
    uint32_t bB = (uint32_t)__cvta_generic_to_shared(&sm->B[0][0]);
    int t = threadIdx.x;
#pragma unroll
    for (int p = 0; p < 2; p++) {
        int idx = t + p * 256;
        int row = idx >> 2, seg = idx & 3;
        uint32_t soff = (uint32_t)(row * SPAD + seg * 8) * 2;
        int grow = row0 + row;
        int pred = (grow < N_NODES) ? 16 : 0;
        long aoff = (long)min(grow, N_NODES - 1) * asr + ka + seg * 8;
        cpa16(bA + soff, A + aoff, pred);
        long boff = (long)(coln0 + row) * bsr + kb + seg * 8;
        cpa16(bB + soff, B + boff, 16);
    }
    asm volatile("cp.async.commit_group;");
}

__device__ __forceinline__ void mma_chunk(GemmSmem* sm, float acc[2][8][4],
                                          int wm, int wn, int lane) {
    uint32_t baseA = (uint32_t)__cvta_generic_to_shared(&sm->A[0][0]);
    uint32_t baseB = (uint32_t)__cvta_generic_to_shared(&sm->B[0][0]);
#pragma unroll
    for (int ks = 0; ks < 2; ks++) {
        uint32_t a[2][4];
#pragma unroll
        for (int mi = 0; mi < 2; mi++) {
            int row = wm * 32 + mi * 16 + (lane & 15);
            int col = ks * 16 + ((lane >> 4) << 3);
            uint32_t off = (uint32_t)(row * SPAD + col) * 2;
            ldsm_x4(a[mi][0], a[mi][1], a[mi][2], a[mi][3], baseA + off);
        }
#pragma unroll
        for (int nj = 0; nj < 4; nj++) {
            int row = wn * 64 + nj * 16 + ((lane >> 4) << 3) + (lane & 7);
            int col = ks * 16 + ((lane >> 3) & 1) * 8;
            uint32_t off = (uint32_t)(row * SPAD + col) * 2;
            uint32_t b0, b1, b2, b3;
            ldsm_x4(b0, b1, b2, b3, baseB + off);
#pragma unroll
            for (int mi = 0; mi < 2; mi++) {
                mma_fp16(acc[mi][nj * 2 + 0], a[mi], b0, b1);
                mma_fp16(acc[mi][nj * 2 + 1], a[mi], b2, b3);
            }
        }
    }
}

// gemm1a (side stream): h_part = x @ W1r + b1  -> fp32 g_hp
__global__ __launch_bounds__(256, 2)
void gemm1a_tc(const float* __restrict__ b1) {
    extern __shared__ __align__(16) char smraw[];
    GemmSmem* st = (GemmSmem*)smraw;
    float acc[2][8][4];
#pragma unroll
    for (int i = 0; i < 2; i++)
#pragma unroll
        for (int j = 0; j < 8; j++)
#pragma unroll
            for (int k = 0; k < 4; k++) acc[i][j][k] = 0.f;

    int lane = threadIdx.x & 31;
    int wid  = threadIdx.x >> 5;
    int wm = wid & 3, wn = wid >> 2;
    int row0 = blockIdx.x * GBM;
    int col0 = blockIdx.y * GBN;
    const int NC = 8;    // K = 256 (x half, W1 cols 256..511)

    auto issue = [&](int c) {
        int k0 = c * GBK;
        load_chunk(&st[c % NSTAGE], g_xf, row0, k0, D_IN,
                   g_w1, col0, 256 + k0, 2 * D_IN);
    };

    issue(0); issue(1); issue(2);
#pragma unroll 1
    for (int c = 0; c < NC; c++) {
        pipe_wait(c, NC);
        __syncthreads();
        mma_chunk(&st[c % NSTAGE], acc, wm, wn, lane);
        if (c + 3 < NC) issue(c + 3);
    }

    int g = lane >> 2, tg = lane & 3;
#pragma unroll
    for (int mi = 0; mi < 2; mi++) {
        int r = row0 + wm * 32 + mi * 16 + g;
#pragma unroll
        for (int t = 0; t < 8; t++) {
            int c = col0 + wn * 64 + t * 8 + tg * 2;
            float bb0 = b1[c], bb1 = b1[c + 1];
            if (r < N_NODES) {
                float2 o = make_float2(acc[mi][t][0] + bb0, acc[mi][t][1] + bb1);
                *(float2*)(g_hp + (long)r * D_HID + c) = o;
            }
            if (r + 8 < N_NODES) {
                float2 o = make_float2(acc[mi][t][2] + bb0, acc[mi][t][3] + bb1);
                *(float2*)(g_hp + (long)(r + 8) * D_HID + c) = o;
            }
        }
    }
}

// gemm1b (main): h = relu(mean1 @ W1l + h_part) -> fp16 g_hf
__global__ __launch_bounds__(256, 2)
void gemm1b_tc() {
    extern __shared__ __align__(16) char smraw[];
    GemmSmem* st = (GemmSmem*)smraw;
    float acc[2][8][4];
#pragma unroll
    for (int i = 0; i < 2; i++)
#pragma unroll
        for (int j = 0; j < 8; j++)
#pragma unroll
            for (int k = 0; k < 4; k++) acc[i][j][k] = 0.f;

    int lane = threadIdx.x & 31;
    int wid  = threadIdx.x >> 5;
    int wm = wid & 3, wn = wid >> 2;
    int row0 = blockIdx.x * GBM;
    int col0 = blockIdx.y * GBN;
    const int NC = 8;    // K = 256 (mean1 half, W1 cols 0..255)

    auto issue = [&](int c) {
        int k0 = c * GBK;
        load_chunk(&st[c % NSTAGE], g_m1, row0, k0, D_IN,
                   g_w1, col0, k0, 2 * D_IN);
    };

    issue(0); issue(1); issue(2);
#pragma unroll 1
    for (int c = 0; c < NC; c++) {
        pipe_wait(c, NC);
        __syncthreads();
        mma_chunk(&st[c % NSTAGE], acc, wm, wn, lane);
        if (c + 3 < NC) issue(c + 3);
    }

    int g = lane >> 2, tg = lane & 3;
#pragma unroll
    for (int mi = 0; mi < 2; mi++) {
        int r = row0 + wm * 32 + mi * 16 + g;
#pragma unroll
        for (int t = 0; t < 8; t++) {
            int c = col0 + wn * 64 + t * 8 + tg * 2;
            if (r < N_NODES) {
                float2 hp = *(const float2*)(g_hp + (long)r * D_HID + c);
                float v0 = fmaxf(acc[mi][t][0] + hp.x, 0.f);
                float v1 = fmaxf(acc[mi][t][1] + hp.y, 0.f);
                *(uint32_t*)(g_hf + (long)r * D_HID + c) =
                    hpack(__float2half(v0), __float2half(v1));
            }
            if (r + 8 < N_NODES) {
                float2 hp = *(const float2*)(g_hp + (long)(r + 8) * D_HID + c);
                float v0 = fmaxf(acc[mi][t][2] + hp.x, 0.f);
                float v1 = fmaxf(acc[mi][t][3] + hp.y, 0.f);
                *(uint32_t*)(g_hf + (long)(r + 8) * D_HID + c) =
                    hpack(__float2half(v0), __float2half(v1));
            }
        }
    }
}

// [y2|z2] = h @ [W2l|W2r] (+b2 on z2 half); y2 stored fp16
__global__ __launch_bounds__(256, 2)
void gemm2_tc(const float* __restrict__ b2) {
    extern __shared__ __align__(16) char smraw[];
    GemmSmem* st = (GemmSmem*)smraw;
    float acc[2][8][4];
#pragma unroll
    for (int i = 0; i < 2; i++)
#pragma unroll
        for (int j = 0; j < 8; j++)
#pragma unroll
            for (int k = 0; k < 4; k++) acc[i][j][k] = 0.f;

    int lane = threadIdx.x & 31;
    int wid  = threadIdx.x >> 5;
    int wm = wid & 3, wn = wid >> 2;
    int row0 = blockIdx.x * GBM;
    int col0 = blockIdx.y * GBN;
    const int NC = 8;    // K = 256

    auto issue = [&](int c) {
        int k0 = c * GBK;
        load_chunk(&st[c % NSTAGE], g_hf, row0, k0, D_HID, g_w2, col0, k0, D_HID);
    };

    issue(0); issue(1); issue(2);
#pragma unroll 1
    for (int c = 0; c < NC; c++) {
        pipe_wait(c, NC);
        __syncthreads();
        mma_chunk(&st[c % NSTAGE], acc, wm, wn, lane);
        if (c + 3 < NC) issue(c + 3);
    }

    int g = lane >> 2, tg = lane & 3;
#pragma unroll
    for (int mi = 0; mi < 2; mi++) {
        int r = row0 + wm * 32 + mi * 16 + g;
#pragma unroll
        for (int t = 0; t < 8; t++) {
            int cg = col0 + wn * 64 + t * 8 + tg * 2;   // 0..255
            bool zside = (cg >= 128);
            int cl = zside ? cg - 128 : cg;
            if (!zside) {
                if (r < N_NODES)
                    *(uint32_t*)(g_y2f + (long)r * D_OUT + cl) =
                        hpack(__float2half(acc[mi][t][0]), __float2half(acc[mi][t][1]));
                if (r + 8 < N_NODES)
                    *(uint32_t*)(g_y2f + (long)(r + 8) * D_OUT + cl) =
                        hpack(__float2half(acc[mi][t][2]), __float2half(acc[mi][t][3]));
            } else {
                float bb0 = b2[cl], bb1 = b2[cl + 1];
                if (r < N_NODES) {
                    float2 o = make_float2(acc[mi][t][0] + bb0, acc[mi][t][1] + bb1);
                    *(float2*)(g_z2 + (long)r * D_OUT + cl) = o;
                }
                if (r + 8 < N_NODES) {
                    float2 o = make_float2(acc[mi][t][2] + bb0, acc[mi][t][3] + bb1);
                    *(float2*)(g_z2 + (long)(r + 8) * D_OUT + cl) = o;
                }
            }
        }
    }
}

// ---- gather2 + final: out = mean(fp16 y2 over in-neighbors) + z2 ----
__device__ __forceinline__ void acc_row8(float& a0, float& a1, float& a2, float& a3,
                                         const uint2& p) {
    float2 fa = __half22float2(*(const __half2*)&p.x);
    float2 fb = __half22float2(*(const __half2*)&p.y);
    a0 += fa.x; a1 += fa.y; a2 += fb.x; a3 += fb.y;
}

__global__ void gather2_final_kernel(float* __restrict__ out) {
    int node = (int)((blockIdx.x * (long)blockDim.x + threadIdx.x) >> 5);
    int lane = threadIdx.x & 31;
    if (node >= N_NODES) return;
    int s = g_rowstart[node], e = g_rowstart[node + 1];
    float a0 = 0.f, a1 = 0.f, a2 = 0.f, a3 = 0.f;
    int i = s;
    for (; i + 8 <= e; i += 8) {
        uint2 p[8];
#pragma unroll
        for (int u = 0; u < 8; u++)
            p[u] = ((const uint2*)(g_y2f + (long)g_csr[i + u] * D_OUT))[lane];
#pragma unroll
        for (int u = 0; u < 8; u++) acc_row8(a0, a1, a2, a3, p[u]);
    }
    for (; i + 4 <= e; i += 4) {
        uint2 p[4];
#pragma unroll
        for (int u = 0; u < 4; u++)
            p[u] = ((const uint2*)(g_y2f + (long)g_csr[i + u] * D_OUT))[lane];
#pragma unroll
        for (int u = 0; u < 4; u++) acc_row8(a0, a1, a2, a3, p[u]);
    }
    for (; i < e; i++) {
        uint2 p = ((const uint2*)(g_y2f + (long)g_csr[i] * D_OUT))[lane];
        acc_row8(a0, a1, a2, a3, p);
    }
    float r = 1.0f / fmaxf((float)(e - s), 1.0f);
    float4 z = ((const float4*)(g_z2 + (long)node * D_OUT))[lane];
    float4 o;
    o.x = a0 * r + z.x;
    o.y = a1 * r + z.y;
    o.z = a2 * r + z.z;
    o.w = a3 * r + z.w;
    ((float4*)(out + (long)node * D_OUT))[lane] = o;
}

extern "C" void kernel_launch(void* const* d_in, const int* in_sizes, int n_in,
                              void* d_out, int out_size) {
    const float* x   = (const float*)d_in[0];
    const int*   ei  = (const int*)d_in[1];
    const float* W1l = (const float*)d_in[2];
    const float* b1  = (const float*)d_in[3];
    const float* W1r = (const float*)d_in[4];
    const float* W2l = (const float*)d_in[5];
    const float* b2  = (const float*)d_in[6];
    const float* W2r = (const float*)d_in[7];
    float* out = (float*)d_out;

    static cudaStream_t s_side = nullptr;
    static cudaEvent_t  s_evFork = nullptr, s_evPrep = nullptr, s_evJoin = nullptr;
    if (s_side == nullptr) {
        cudaStreamCreateWithFlags(&s_side, cudaStreamNonBlocking);
        cudaEventCreateWithFlags(&s_evFork, cudaEventDisableTiming);
        cudaEventCreateWithFlags(&s_evPrep, cudaEventDisableTiming);
        cudaEventCreateWithFlags(&s_evJoin, cudaEventDisableTiming);
    }

    cudaFuncSetAttribute(gemm1a_tc, cudaFuncAttributeMaxDynamicSharedMemorySize,
                         (int)GEMM_SMEM_BYTES);
    cudaFuncSetAttribute(gemm1b_tc, cudaFuncAttributeMaxDynamicSharedMemorySize,
                         (int)GEMM_SMEM_BYTES);
    cudaFuncSetAttribute(gemm2_tc, cudaFuncAttributeMaxDynamicSharedMemorySize,
                         (int)GEMM_SMEM_BYTES);

    // Fork: side stream runs prep then gemm1a (x@W1r half — no graph dep),
    // concurrent with the CSR build + gather1 on the main stream.
    cudaEventRecord(s_evFork, 0);
    cudaStreamWaitEvent(s_side, s_evFork, 0);
    prep_kernel<<<(N_NODES * D_IN / 4 + 255) / 256, 256, 0, s_side>>>(
        x, W1l, W1r, W2l, W2r);
    cudaEventRecord(s_evPrep, s_side);
    gemm1a_tc<<<dim3((N_NODES + GBM - 1) / GBM, 2), 256, GEMM_SMEM_BYTES, s_side>>>(b1);
    cudaEventRecord(s_evJoin, s_side);

    zero_deg_kernel<<<(N_NODES + 255) / 256, 256>>>();
    degree_kernel<<<(N_EDGES / 4 + 255) / 256, 256>>>(ei);
    scan_p1_kernel<<<SCAN_NB, SCAN_B>>>();
    scan_p2_kernel<<<1, 64>>>();
    scan_p3_kernel<<<SCAN_NB, SCAN_B>>>();
    fill_kernel<<<(N_EDGES / 4 + 255) / 256, 256>>>(ei);

    // gather1 needs g_xf (prep) + CSR (fill)
    cudaStreamWaitEvent(0, s_evPrep, 0);
    gather1_kernel<<<(N_NODES * 32 + 255) / 256, 256>>>();

    // gemm1b needs mean1 (gather1) + h_part (gemm1a)
    cudaStreamWaitEvent(0, s_evJoin, 0);
    gemm1b_tc<<<dim3((N_NODES + GBM - 1) / GBM, 2), 256, GEMM_SMEM_BYTES>>>();
    gemm2_tc<<<dim3((N_NODES + GBM - 1) / GBM, 2), 256, GEMM_SMEM_BYTES>>>(b2);

    gather2_final_kernel<<<(N_NODES * 32 + 255) / 256, 256>>>(out);
}

// round 15
// speedup vs baseline: 1.1547x; 1.1547x over previous
#include <cuda_runtime.h>
#include <cuda_fp16.h>
#include <cstdint>

#define N_NODES 50000
#define N_EDGES 800000
#define D_IN    256
#define D_HID   256
#define D_OUT   128

#define SCAN_B   1024
#define SCAN_NB  ((N_NODES + SCAN_B - 1) / SCAN_B)   // 49

// ---- scratch (no allocations allowed) ----
__device__ __half g_xf [N_NODES * D_IN];    // fp16(x)
__device__ __half g_m1 [N_NODES * D_IN];    // fp16(mean1)
__device__ __half g_hf [N_NODES * D_HID];   // fp16(h)
__device__ __half g_w1 [D_HID * 2 * D_IN];  // B1^T: [256 n][512 k]
__device__ __half g_w2 [2 * D_OUT * D_HID]; // B2^T: [256 n][256 k]
__device__ __half g_y2f[N_NODES * D_OUT];   // fp16(h @ W2_l)
__device__ float g_z2[N_NODES * D_OUT];     // h @ W2_r + b2
__device__ int   g_deg[N_NODES];
__device__ int   g_rowstart[N_NODES + 1];
__device__ int   g_cursor[N_NODES];         // phase1 temp: inclusive prefix
__device__ int   g_csr[N_EDGES];
__device__ int   g_bsum[SCAN_NB];

__device__ __forceinline__ int clampi(int v) {
    return min(max(v, 0), N_NODES - 1);
}

__device__ __forceinline__ uint32_t hpack(__half a, __half b) {
    union { __half2 v; uint32_t u; } t;
    t.v.x = a; t.v.y = b;
    return t.u;
}

// ---- per-launch reset ----
__global__ void zero_deg_kernel() {
    int i = blockIdx.x * blockDim.x + threadIdx.x;
    if (i < N_NODES) g_deg[i] = 0;
}

// ---- prep: convert x + transposed fp16 weights (side stream) ----
__global__ void prep_kernel(const float* __restrict__ x,
                            const float* __restrict__ W1l,
                            const float* __restrict__ W1r,
                            const float* __restrict__ W2l,
                            const float* __restrict__ W2r) {
    int idx = blockIdx.x * blockDim.x + threadIdx.x;
    const int nx = N_NODES * D_IN / 4;
    if (idx < nx) {
        float4 v = ((const float4*)x)[idx];
        ((uint2*)g_xf)[idx] = make_uint2(
            hpack(__float2half(v.x), __float2half(v.y)),
            hpack(__float2half(v.z), __float2half(v.w)));
    }
    const int n1 = D_HID * 2 * D_IN;       // 131072
    const int n2 = 2 * D_OUT * D_HID;      // 65536
    if (idx < n1) {
        int n = idx >> 9, k = idx & 511;
        float v = (k < 256) ? W1l[k * D_HID + n] : W1r[(k - 256) * D_HID + n];
        g_w1[idx] = __float2half(v);
    }
    if (idx < n2) {
        int n = idx >> 8, k = idx & 255;
        float v = (n < 128) ? W2l[k * D_OUT + n] : W2r[k * D_OUT + (n - 128)];
        g_w2[idx] = __float2half(v);
    }
}

// ---- CSR build ----
__global__ void degree_kernel(const int* __restrict__ ei) {
    int i = blockIdx.x * blockDim.x + threadIdx.x;
    if (i >= N_EDGES / 4) return;
    int4 d = ((const int4*)(ei + N_EDGES))[i];
    atomicAdd(&g_deg[clampi(d.x)], 1);
    atomicAdd(&g_deg[clampi(d.y)], 1);
    atomicAdd(&g_deg[clampi(d.z)], 1);
    atomicAdd(&g_deg[clampi(d.w)], 1);
}

// phase 1: block-local inclusive scan; totals to g_bsum, prefix to g_cursor (temp)
__global__ void scan_p1_kernel() {
    __shared__ int sh[SCAN_B];
    int t = threadIdx.x;
    int i = blockIdx.x * SCAN_B + t;
    int d = (i < N_NODES) ? g_deg[i] : 0;
    sh[t] = d;
    __syncthreads();
#pragma unroll
    for (int off = 1; off < SCAN_B; off <<= 1) {
        int v = (t >= off) ? sh[t - off] : 0;
        __syncthreads();
        sh[t] += v;
        __syncthreads();
    }
    if (i < N_NODES) g_cursor[i] = sh[t];       // inclusive prefix (local)
    if (t == SCAN_B - 1) g_bsum[blockIdx.x] = sh[t];
}

// phase 3 (p2 folded in): each block rescans the 49 block totals locally,
// derives its own offset; block 0 also writes rowstart[N_NODES].
__global__ void scan_p3_kernel() {
    __shared__ int sh[64];
    int t = threadIdx.x;
    if (t < 64) sh[t] = (t < SCAN_NB) ? g_bsum[t] : 0;
    __syncthreads();
#pragma unroll
    for (int off = 1; off < 64; off <<= 1) {
        int v = (t >= off && t < 64) ? sh[t - off] : 0;
        __syncthreads();
        if (t < 64) sh[t] += v;
        __syncthreads();
    }
    int boff = (blockIdx.x == 0) ? 0 : sh[blockIdx.x - 1];
    if (blockIdx.x == 0 && t == 0) g_rowstart[N_NODES] = sh[SCAN_NB - 1];
    int i = blockIdx.x * SCAN_B + t;
    if (i < N_NODES) {
        int ex = g_cursor[i] - g_deg[i] + boff;
        g_rowstart[i] = ex;
        g_cursor[i] = ex;
    }
}

__global__ void fill_kernel(const int* __restrict__ ei) {
    int i = blockIdx.x * blockDim.x + threadIdx.x;
    if (i >= N_EDGES / 4) return;
    int4 d = ((const int4*)(ei + N_EDGES))[i];
    int4 s = ((const int4*)ei)[i];
    int slot;
    slot = atomicAdd(&g_cursor[clampi(d.x)], 1); g_csr[slot] = clampi(s.x);
    slot = atomicAdd(&g_cursor[clampi(d.y)], 1); g_csr[slot] = clampi(s.y);
    slot = atomicAdd(&g_cursor[clampi(d.z)], 1); g_csr[slot] = clampi(s.z);
    slot = atomicAdd(&g_cursor[clampi(d.w)], 1); g_csr[slot] = clampi(s.w);
}

// ---- gather1: mean of fp16 x over in-neighbors -> fp16 (warp per node) ----
__device__ __forceinline__ void acc_row16(float* acc, const uint4& p) {
    float2 f0 = __half22float2(*(const __half2*)&p.x);
    float2 f1 = __half22float2(*(const __half2*)&p.y);
    float2 f2 = __half22float2(*(const __half2*)&p.z);
    float2 f3 = __half22float2(*(const __half2*)&p.w);
    acc[0] += f0.x; acc[1] += f0.y; acc[2] += f1.x; acc[3] += f1.y;
    acc[4] += f2.x; acc[5] += f2.y; acc[6] += f3.x; acc[7] += f3.y;
}

__global__ void gather1_kernel() {
    int node = (int)((blockIdx.x * (long)blockDim.x + threadIdx.x) >> 5);
    int lane = threadIdx.x & 31;
    if (node >= N_NODES) return;
    int s = g_rowstart[node], e = g_rowstart[node + 1];
    float acc[8];
#pragma unroll
    for (int j = 0; j < 8; j++) acc[j] = 0.f;
    int i = s;
    for (; i + 8 <= e; i += 8) {
        uint4 p[8];
#pragma unroll
        for (int u = 0; u < 8; u++)
            p[u] = ((const uint4*)(g_xf + (long)g_csr[i + u] * D_IN))[lane];
#pragma unroll
        for (int u = 0; u < 8; u++) acc_row16(acc, p[u]);
    }
    for (; i + 4 <= e; i += 4) {
        uint4 p[4];
#pragma unroll
        for (int u = 0; u < 4; u++)
            p[u] = ((const uint4*)(g_xf + (long)g_csr[i + u] * D_IN))[lane];
#pragma unroll
        for (int u = 0; u < 4; u++) acc_row16(acc, p[u]);
    }
    for (; i < e; i++) {
        uint4 p = ((const uint4*)(g_xf + (long)g_csr[i] * D_IN))[lane];
        acc_row16(acc, p);
    }
    float r = 1.0f / fmaxf((float)(e - s), 1.0f);
    uint4 p = make_uint4(
        hpack(__float2half(acc[0] * r), __float2half(acc[1] * r)),
        hpack(__float2half(acc[2] * r), __float2half(acc[3] * r)),
        hpack(__float2half(acc[4] * r), __float2half(acc[5] * r)),
        hpack(__float2half(acc[6] * r), __float2half(acc[7] * r)));
    ((uint4*)(g_m1 + (long)node * D_IN))[lane] = p;
}

// ======================================================================
// fp16 single-pass tensor GEMM. Block 128x128, BK=32, 256 thr, 8 warps.
// 4-stage cp.async pipeline, ONE __syncthreads per iteration.
// ======================================================================
#define GBM 128
#define GBN 128
#define GBK 32
#define SPAD 40
#define NSTAGE 4

struct GemmSmem {
    __half A[GBM][SPAD];
    __half B[GBN][SPAD];
};
#define GEMM_SMEM_BYTES (NSTAGE * sizeof(GemmSmem))

__device__ __forceinline__ void cpa16(uint32_t dst, const void* src, int srcsize) {
    asm volatile("cp.async.cg.shared.global [%0], [%1], 16, %2;"
                 :: "r"(dst), "l"(src), "r"(srcsize));
}

__device__ __forceinline__ void ldsm_x4(uint32_t& r0, uint32_t& r1,
                                        uint32_t& r2, uint32_t& r3, uint32_t addr) {
    asm volatile("ldmatrix.sync.aligned.m8n8.x4.shared.b16 {%0,%1,%2,%3}, [%4];"
                 : "=r"(r0), "=r"(r1), "=r"(r2), "=r"(r3) : "r"(addr));
}

__device__ __forceinline__ void mma_fp16(float* d, const uint32_t* a,
                                         uint32_t b0, uint32_t b1) {
    asm volatile(
        "mma.sync.aligned.m16n8k16.row.col.f32.f16.f16.f32 "
        "{%0,%1,%2,%3}, {%4,%5,%6,%7}, {%8,%9}, {%0,%1,%2,%3};"
        : "+f"(d[0]), "+f"(d[1]), "+f"(d[2]), "+f"(d[3])
        : "r"(a[0]), "r"(a[1]), "r"(a[2]), "r"(a[3]), "r"(b0), "r"(b1));
}

__device__ __forceinline__ void pipe_wait(int c, int NC) {
    if (c < NC - 2)       asm volatile("cp.async.wait_group 2;");
    else if (c == NC - 2) asm volatile("cp.async.wait_group 1;");
    else                  asm volatile("cp.async.wait_group 0;");
}

__device__ __forceinline__ void load_chunk(GemmSmem* sm,
        const __half* A, int row0, int ka, int asr,
        const __half* B, int coln0, int kb, int bsr) {
    uint32_t bA = (uint32_t)__cvta_generic_to_shared(&sm->A[0][0]);
    uint32_t bB = (uint32_t)__cvta_generic_to_shared(&sm->B[0][0]);
    int t = threadIdx.x;
#pragma unroll
    for (int p = 0; p < 2; p++) {
        int idx = t + p * 256;
        int row = idx >> 2, seg = idx & 3;
        uint32_t soff = (uint32_t)(row * SPAD + seg * 8) * 2;
        int grow = row0 + row;
        int pred = (grow < N_NODES) ? 16 : 0;
        long aoff = (long)min(grow, N_NODES - 1) * asr + ka + seg * 8;
        cpa16(bA + soff, A + aoff, pred);
        long boff = (long)(coln0 + row) * bsr + kb + seg * 8;
        cpa16(bB + soff, B + boff, 16);
    }
    asm volatile("cp.async.commit_group;");
}

__device__ __forceinline__ void mma_chunk(GemmSmem* sm, float acc[2][8][4],
                                          int wm, int wn, int lane) {
    uint32_t baseA = (uint32_t)__cvta_generic_to_shared(&sm->A[0][0]);
    uint32_t baseB = (uint32_t)__cvta_generic_to_shared(&sm->B[0][0]);
#pragma unroll
    for (int ks = 0; ks < 2; ks++) {
        uint32_t a[2][4];
#pragma unroll
        for (int mi = 0; mi < 2; mi++) {
            int row = wm * 32 + mi * 16 + (lane & 15);
            int col = ks * 16 + ((lane >> 4) << 3);
            uint32_t off = (uint32_t)(row * SPAD + col) * 2;
            ldsm_x4(a[mi][0], a[mi][1], a[mi][2], a[mi][3], baseA + off);
        }
#pragma unroll
        for (int nj = 0; nj < 4; nj++) {
            int row = wn * 64 + nj * 16 + ((lane >> 4) << 3) + (lane & 7);
            int col = ks * 16 + ((lane >> 3) & 1) * 8;
            uint32_t off = (uint32_t)(row * SPAD + col) * 2;
            uint32_t b0, b1, b2, b3;
            ldsm_x4(b0, b1, b2, b3, baseB + off);
#pragma unroll
            for (int mi = 0; mi < 2; mi++) {
                mma_fp16(acc[mi][nj * 2 + 0], a[mi], b0, b1);
                mma_fp16(acc[mi][nj * 2 + 1], a[mi], b2, b3);
            }
        }
    }
}

// h = relu([mean1|x] @ [W1l;W1r] + b1) -> fp16
__global__ __launch_bounds__(256, 2)
void gemm1_tc(const float* __restrict__ b1) {
    extern __shared__ __align__(16) char smraw[];
    GemmSmem* st = (GemmSmem*)smraw;
    float acc[2][8][4];
#pragma unroll
    for (int i = 0; i < 2; i++)
#pragma unroll
        for (int j = 0; j < 8; j++)
#pragma unroll
            for (int k = 0; k < 4; k++) acc[i][j][k] = 0.f;

    int lane = threadIdx.x & 31;
    int wid  = threadIdx.x >> 5;
    int wm = wid & 3, wn = wid >> 2;
    int row0 = blockIdx.x * GBM;
    int col0 = blockIdx.y * GBN;
    const int NC = 16;   // K = 512

    auto issue = [&](int c) {
        int k0 = c * GBK;
        const __half* As;
        int kk;
        if (k0 < 256) { As = g_m1; kk = k0; }
        else          { As = g_xf; kk = k0 - 256; }
        load_chunk(&st[c % NSTAGE], As, row0, kk, D_IN, g_w1, col0, k0, 2 * D_IN);
    };

    issue(0);
    issue(1);
    issue(2);
#pragma unroll 1
    for (int c = 0; c < NC; c++) {
        pipe_wait(c, NC);
        __syncthreads();
        mma_chunk(&st[c % NSTAGE], acc, wm, wn, lane);
        if (c + 3 < NC) issue(c + 3);
    }

    int g = lane >> 2, tg = lane & 3;
#pragma unroll
    for (int mi = 0; mi < 2; mi++) {
        int r = row0 + wm * 32 + mi * 16 + g;
#pragma unroll
        for (int t = 0; t < 8; t++) {
            int c = col0 + wn * 64 + t * 8 + tg * 2;
            float bb0 = b1[c], bb1 = b1[c + 1];
            if (r < N_NODES) {
                float v0 = fmaxf(acc[mi][t][0] + bb0, 0.f);
                float v1 = fmaxf(acc[mi][t][1] + bb1, 0.f);
                *(uint32_t*)(g_hf + (long)r * D_HID + c) =
                    hpack(__float2half(v0), __float2half(v1));
            }
            if (r + 8 < N_NODES) {
                float v0 = fmaxf(acc[mi][t][2] + bb0, 0.f);
                float v1 = fmaxf(acc[mi][t][3] + bb1, 0.f);
                *(uint32_t*)(g_hf + (long)(r + 8) * D_HID + c) =
                    hpack(__float2half(v0), __float2half(v1));
            }
        }
    }
}

// [y2|z2] = h @ [W2l|W2r] (+b2 on z2 half); y2 stored fp16
__global__ __launch_bounds__(256, 2)
void gemm2_tc(const float* __restrict__ b2) {
    extern __shared__ __align__(16) char smraw[];
    GemmSmem* st = (GemmSmem*)smraw;
    float acc[2][8][4];
#pragma unroll
    for (int i = 0; i < 2; i++)
#pragma unroll
        for (int j = 0; j < 8; j++)
#pragma unroll
            for (int k = 0; k < 4; k++) acc[i][j][k] = 0.f;

    int lane = threadIdx.x & 31;
    int wid  = threadIdx.x >> 5;
    int wm = wid & 3, wn = wid >> 2;
    int row0 = blockIdx.x * GBM;
    int col0 = blockIdx.y * GBN;
    const int NC = 8;    // K = 256

    auto issue = [&](int c) {
        int k0 = c * GBK;
        load_chunk(&st[c % NSTAGE], g_hf, row0, k0, D_HID, g_w2, col0, k0, D_HID);
    };

    issue(0);
    issue(1);
    issue(2);
#pragma unroll 1
    for (int c = 0; c < NC; c++) {
        pipe_wait(c, NC);
        __syncthreads();
        mma_chunk(&st[c % NSTAGE], acc, wm, wn, lane);
        if (c + 3 < NC) issue(c + 3);
    }

    int g = lane >> 2, tg = lane & 3;
#pragma unroll
    for (int mi = 0; mi < 2; mi++) {
        int r = row0 + wm * 32 + mi * 16 + g;
#pragma unroll
        for (int t = 0; t < 8; t++) {
            int cg = col0 + wn * 64 + t * 8 + tg * 2;   // 0..255
            bool zside = (cg >= 128);
            int cl = zside ? cg - 128 : cg;
            if (!zside) {
                if (r < N_NODES)
                    *(uint32_t*)(g_y2f + (long)r * D_OUT + cl) =
                        hpack(__float2half(acc[mi][t][0]), __float2half(acc[mi][t][1]));
                if (r + 8 < N_NODES)
                    *(uint32_t*)(g_y2f + (long)(r + 8) * D_OUT + cl) =
                        hpack(__float2half(acc[mi][t][2]), __float2half(acc[mi][t][3]));
            } else {
                float bb0 = b2[cl], bb1 = b2[cl + 1];
                if (r < N_NODES) {
                    float2 o = make_float2(acc[mi][t][0] + bb0, acc[mi][t][1] + bb1);
                    *(float2*)(g_z2 + (long)r * D_OUT + cl) = o;
                }
                if (r + 8 < N_NODES) {
                    float2 o = make_float2(acc[mi][t][2] + bb0, acc[mi][t][3] + bb1);
                    *(float2*)(g_z2 + (long)(r + 8) * D_OUT + cl) = o;
                }
            }
        }
    }
}

// ---- gather2 + final: out = mean(fp16 y2 over in-neighbors) + z2 ----
__device__ __forceinline__ void acc_row8(float& a0, float& a1, float& a2, float& a3,
                                         const uint2& p) {
    float2 fa = __half22float2(*(const __half2*)&p.x);
    float2 fb = __half22float2(*(const __half2*)&p.y);
    a0 += fa.x; a1 += fa.y; a2 += fb.x; a3 += fb.y;
}

__global__ void gather2_final_kernel(float* __restrict__ out) {
    int node = (int)((blockIdx.x * (long)blockDim.x + threadIdx.x) >> 5);
    int lane = threadIdx.x & 31;
    if (node >= N_NODES) return;
    int s = g_rowstart[node], e = g_rowstart[node + 1];
    float a0 = 0.f, a1 = 0.f, a2 = 0.f, a3 = 0.f;
    int i = s;
    for (; i + 8 <= e; i += 8) {
        uint2 p[8];
#pragma unroll
        for (int u = 0; u < 8; u++)
            p[u] = ((const uint2*)(g_y2f + (long)g_csr[i + u] * D_OUT))[lane];
#pragma unroll
        for (int u = 0; u < 8; u++) acc_row8(a0, a1, a2, a3, p[u]);
    }
    for (; i + 4 <= e; i += 4) {
        uint2 p[4];
#pragma unroll
        for (int u = 0; u < 4; u++)
            p[u] = ((const uint2*)(g_y2f + (long)g_csr[i + u] * D_OUT))[lane];
#pragma unroll
        for (int u = 0; u < 4; u++) acc_row8(a0, a1, a2, a3, p[u]);
    }
    for (; i < e; i++) {
        uint2 p = ((const uint2*)(g_y2f + (long)g_csr[i] * D_OUT))[lane];
        acc_row8(a0, a1, a2, a3, p);
    }
    float r = 1.0f / fmaxf((float)(e - s), 1.0f);
    float4 z = ((const float4*)(g_z2 + (long)node * D_OUT))[lane];
    float4 o;
    o.x = a0 * r + z.x;
    o.y = a1 * r + z.y;
    o.z = a2 * r + z.z;
    o.w = a3 * r + z.w;
    ((float4*)(out + (long)node * D_OUT))[lane] = o;
}

extern "C" void kernel_launch(void* const* d_in, const int* in_sizes, int n_in,
                              void* d_out, int out_size) {
    const float* x   = (const float*)d_in[0];
    const int*   ei  = (const int*)d_in[1];
    const float* W1l = (const float*)d_in[2];
    const float* b1  = (const float*)d_in[3];
    const float* W1r = (const float*)d_in[4];
    const float* W2l = (const float*)d_in[5];
    const float* b2  = (const float*)d_in[6];
    const float* W2r = (const float*)d_in[7];
    float* out = (float*)d_out;

    static cudaStream_t s_side = nullptr;
    static cudaEvent_t  s_evFork = nullptr, s_evJoin = nullptr;
    if (s_side == nullptr) {
        cudaStreamCreateWithFlags(&s_side, cudaStreamNonBlocking);
        cudaEventCreateWithFlags(&s_evFork, cudaEventDisableTiming);
        cudaEventCreateWithFlags(&s_evJoin, cudaEventDisableTiming);
    }

    cudaFuncSetAttribute(gemm1_tc, cudaFuncAttributeMaxDynamicSharedMemorySize,
                         (int)GEMM_SMEM_BYTES);
    cudaFuncSetAttribute(gemm2_tc, cudaFuncAttributeMaxDynamicSharedMemorySize,
                         (int)GEMM_SMEM_BYTES);

    // Fork: prep on side stream, concurrent with CSR build (disjoint arrays).
    cudaEventRecord(s_evFork, 0);
    cudaStreamWaitEvent(s_side, s_evFork, 0);
    prep_kernel<<<(N_NODES * D_IN / 4 + 255) / 256, 256, 0, s_side>>>(
        x, W1l, W1r, W2l, W2r);
    cudaEventRecord(s_evJoin, s_side);

    zero_deg_kernel<<<(N_NODES + 255) / 256, 256>>>();
    degree_kernel<<<(N_EDGES / 4 + 255) / 256, 256>>>(ei);
    scan_p1_kernel<<<SCAN_NB, SCAN_B>>>();
    scan_p3_kernel<<<SCAN_NB, SCAN_B>>>();
    fill_kernel<<<(N_EDGES / 4 + 255) / 256, 256>>>(ei);

    // Join: gather1 needs g_xf (prep) + CSR (fill).
    cudaStreamWaitEvent(0, s_evJoin, 0);
    gather1_kernel<<<(N_NODES * 32 + 255) / 256, 256>>>();

    gemm1_tc<<<dim3((N_NODES + GBM - 1) / GBM, 2), 256, GEMM_SMEM_BYTES>>>(b1);
    gemm2_tc<<<dim3((N_NODES + GBM - 1) / GBM, 2), 256, GEMM_SMEM_BYTES>>>(b2);

    gather2_final_kernel<<<(N_NODES * 32 + 255) / 256, 256>>>(out);
}

// round 16
// speedup vs baseline: 1.1578x; 1.0027x over previous
#include <cuda_runtime.h>
#include <cuda_fp16.h>
#include <cstdint>

#define N_NODES 50000
#define N_EDGES 800000
#define D_IN    256
#define D_HID   256
#define D_OUT   128

#define SCAN_B   1024
#define SCAN_NB  ((N_NODES + SCAN_B - 1) / SCAN_B)   // 49

// ---- scratch (no allocations allowed) ----
__device__ __half g_xf [N_NODES * D_IN];    // fp16(x)
__device__ __half g_m1 [N_NODES * D_IN];    // fp16(mean1)
__device__ __half g_hf [N_NODES * D_HID];   // fp16(h)
__device__ __half g_w1 [D_HID * 2 * D_IN];  // B1^T: [256 n][512 k]
__device__ __half g_w2 [2 * D_OUT * D_HID]; // B2^T: [256 n][256 k]
__device__ __half g_y2f[N_NODES * D_OUT];   // fp16(h @ W2_l)
__device__ float g_z2[N_NODES * D_OUT];     // h @ W2_r + b2
__device__ int   g_deg[N_NODES];
__device__ int   g_rowstart[N_NODES + 1];
__device__ int   g_cursor[N_NODES];         // phase1 temp: inclusive prefix
__device__ int   g_csr[N_EDGES];
__device__ int   g_bsum[SCAN_NB];

__device__ __forceinline__ int clampi(int v) {
    return min(max(v, 0), N_NODES - 1);
}

__device__ __forceinline__ uint32_t hpack(__half a, __half b) {
    union { __half2 v; uint32_t u; } t;
    t.v.x = a; t.v.y = b;
    return t.u;
}

// ---- per-launch reset ----
__global__ void zero_deg_kernel() {
    int i = blockIdx.x * blockDim.x + threadIdx.x;
    if (i < N_NODES) g_deg[i] = 0;
}

// ---- prep: convert x + transposed fp16 weights (side stream) ----
__global__ void prep_kernel(const float* __restrict__ x,
                            const float* __restrict__ W1l,
                            const float* __restrict__ W1r,
                            const float* __restrict__ W2l,
                            const float* __restrict__ W2r) {
    int idx = blockIdx.x * blockDim.x + threadIdx.x;
    const int nx = N_NODES * D_IN / 4;
    if (idx < nx) {
        float4 v = ((const float4*)x)[idx];
        ((uint2*)g_xf)[idx] = make_uint2(
            hpack(__float2half(v.x), __float2half(v.y)),
            hpack(__float2half(v.z), __float2half(v.w)));
    }
    const int n1 = D_HID * 2 * D_IN;       // 131072
    const int n2 = 2 * D_OUT * D_HID;      // 65536
    if (idx < n1) {
        int n = idx >> 9, k = idx & 511;
        float v = (k < 256) ? W1l[k * D_HID + n] : W1r[(k - 256) * D_HID + n];
        g_w1[idx] = __float2half(v);
    }
    if (idx < n2) {
        int n = idx >> 8, k = idx & 255;
        float v = (n < 128) ? W2l[k * D_OUT + n] : W2r[k * D_OUT + (n - 128)];
        g_w2[idx] = __float2half(v);
    }
}

// ---- CSR build ----
__global__ void degree_kernel(const int* __restrict__ ei) {
    int i = blockIdx.x * blockDim.x + threadIdx.x;
    if (i >= N_EDGES / 4) return;
    int4 d = ((const int4*)(ei + N_EDGES))[i];
    atomicAdd(&g_deg[clampi(d.x)], 1);
    atomicAdd(&g_deg[clampi(d.y)], 1);
    atomicAdd(&g_deg[clampi(d.z)], 1);
    atomicAdd(&g_deg[clampi(d.w)], 1);
}

// phase 1: block-local inclusive scan; totals to g_bsum, prefix to g_cursor (temp)
__global__ void scan_p1_kernel() {
    __shared__ int sh[SCAN_B];
    int t = threadIdx.x;
    int i = blockIdx.x * SCAN_B + t;
    int d = (i < N_NODES) ? g_deg[i] : 0;
    sh[t] = d;
    __syncthreads();
#pragma unroll
    for (int off = 1; off < SCAN_B; off <<= 1) {
        int v = (t >= off) ? sh[t - off] : 0;
        __syncthreads();
        sh[t] += v;
        __syncthreads();
    }
    if (i < N_NODES) g_cursor[i] = sh[t];       // inclusive prefix (local)
    if (t == SCAN_B - 1) g_bsum[blockIdx.x] = sh[t];
}

// phase 3 (p2 folded in): each block rescans the 49 block totals locally,
// derives its own offset; block 0 also writes rowstart[N_NODES].
__global__ void scan_p3_kernel() {
    __shared__ int sh[64];
    int t = threadIdx.x;
    if (t < 64) sh[t] = (t < SCAN_NB) ? g_bsum[t] : 0;
    __syncthreads();
#pragma unroll
    for (int off = 1; off < 64; off <<= 1) {
        int v = (t >= off && t < 64) ? sh[t - off] : 0;
        __syncthreads();
        if (t < 64) sh[t] += v;
        __syncthreads();
    }
    int boff = (blockIdx.x == 0) ? 0 : sh[blockIdx.x - 1];
    if (blockIdx.x == 0 && t == 0) g_rowstart[N_NODES] = sh[SCAN_NB - 1];
    int i = blockIdx.x * SCAN_B + t;
    if (i < N_NODES) {
        int ex = g_cursor[i] - g_deg[i] + boff;
        g_rowstart[i] = ex;
        g_cursor[i] = ex;
    }
}

__global__ void fill_kernel(const int* __restrict__ ei) {
    int i = blockIdx.x * blockDim.x + threadIdx.x;
    if (i >= N_EDGES / 4) return;
    int4 d = ((const int4*)(ei + N_EDGES))[i];
    int4 s = ((const int4*)ei)[i];
    int slot;
    slot = atomicAdd(&g_cursor[clampi(d.x)], 1); g_csr[slot] = clampi(s.x);
    slot = atomicAdd(&g_cursor[clampi(d.y)], 1); g_csr[slot] = clampi(s.y);
    slot = atomicAdd(&g_cursor[clampi(d.z)], 1); g_csr[slot] = clampi(s.z);
    slot = atomicAdd(&g_cursor[clampi(d.w)], 1); g_csr[slot] = clampi(s.w);
}

// ---- gather1: mean of fp16 x over in-neighbors -> fp16 (warp per node) ----
__device__ __forceinline__ void acc_row16(float* acc, const uint4& p) {
    float2 f0 = __half22float2(*(const __half2*)&p.x);
    float2 f1 = __half22float2(*(const __half2*)&p.y);
    float2 f2 = __half22float2(*(const __half2*)&p.z);
    float2 f3 = __half22float2(*(const __half2*)&p.w);
    acc[0] += f0.x; acc[1] += f0.y; acc[2] += f1.x; acc[3] += f1.y;
    acc[4] += f2.x; acc[5] += f2.y; acc[6] += f3.x; acc[7] += f3.y;
}

__global__ void gather1_kernel() {
    int node = (int)((blockIdx.x * (long)blockDim.x + threadIdx.x) >> 5);
    int lane = threadIdx.x & 31;
    if (node >= N_NODES) return;
    int s = g_rowstart[node], e = g_rowstart[node + 1];
    float acc[8];
#pragma unroll
    for (int j = 0; j < 8; j++) acc[j] = 0.f;
    int i = s;
    for (; i + 8 <= e; i += 8) {
        uint4 p[8];
#pragma unroll
        for (int u = 0; u < 8; u++)
            p[u] = ((const uint4*)(g_xf + (long)g_csr[i + u] * D_IN))[lane];
#pragma unroll
        for (int u = 0; u < 8; u++) acc_row16(acc, p[u]);
    }
    for (; i + 4 <= e; i += 4) {
        uint4 p[4];
#pragma unroll
        for (int u = 0; u < 4; u++)
            p[u] = ((const uint4*)(g_xf + (long)g_csr[i + u] * D_IN))[lane];
#pragma unroll
        for (int u = 0; u < 4; u++) acc_row16(acc, p[u]);
    }
    for (; i < e; i++) {
        uint4 p = ((const uint4*)(g_xf + (long)g_csr[i] * D_IN))[lane];
        acc_row16(acc, p);
    }
    float r = 1.0f / fmaxf((float)(e - s), 1.0f);
    uint4 p = make_uint4(
        hpack(__float2half(acc[0] * r), __float2half(acc[1] * r)),
        hpack(__float2half(acc[2] * r), __float2half(acc[3] * r)),
        hpack(__float2half(acc[4] * r), __float2half(acc[5] * r)),
        hpack(__float2half(acc[6] * r), __float2half(acc[7] * r)));
    ((uint4*)(g_m1 + (long)node * D_IN))[lane] = p;
}

// ======================================================================
// fp16 single-pass tensor GEMM. Block 128x128, BK=32, 256 thr, 8 warps.
// 4-stage cp.async pipeline, ONE __syncthreads per iteration.
// ======================================================================
#define GBM 128
#define GBN 128
#define GBK 32
#define SPAD 40
#define NSTAGE 4

struct GemmSmem {
    __half A[GBM][SPAD];
    __half B[GBN][SPAD];
};
#define GEMM_SMEM_BYTES (NSTAGE * sizeof(GemmSmem))

__device__ __forceinline__ void cpa16(uint32_t dst, const void* src, int srcsize) {
    asm volatile("cp.async.cg.shared.global [%0], [%1], 16, %2;"
                 :: "r"(dst), "l"(src), "r"(srcsize));
}

__device__ __forceinline__ void ldsm_x4(uint32_t& r0, uint32_t& r1,
                                        uint32_t& r2, uint32_t& r3, uint32_t addr) {
    asm volatile("ldmatrix.sync.aligned.m8n8.x4.shared.b16 {%0,%1,%2,%3}, [%4];"
                 : "=r"(r0), "=r"(r1), "=r"(r2), "=r"(r3) : "r"(addr));
}

__device__ __forceinline__ void mma_fp16(float* d, const uint32_t* a,
                                         uint32_t b0, uint32_t b1) {
    asm volatile(
        "mma.sync.aligned.m16n8k16.row.col.f32.f16.f16.f32 "
        "{%0,%1,%2,%3}, {%4,%5,%6,%7}, {%8,%9}, {%0,%1,%2,%3};"
        : "+f"(d[0]), "+f"(d[1]), "+f"(d[2]), "+f"(d[3])
        : "r"(a[0]), "r"(a[1]), "r"(a[2]), "r"(a[3]), "r"(b0), "r"(b1));
}

__device__ __forceinline__ void pipe_wait(int c, int NC) {
    if (c < NC - 2)       asm volatile("cp.async.wait_group 2;");
    else if (c == NC - 2) asm volatile("cp.async.wait_group 1;");
    else                  asm volatile("cp.async.wait_group 0;");
}

__device__ __forceinline__ void load_chunk(GemmSmem* sm,
        const __half* A, int row0, int ka, int asr,
        const __half* B, int coln0, int kb, int bsr) {
    uint32_t bA = (uint32_t)__cvta_generic_to_shared(&sm->A[0][0]);
    uint32_t bB = (uint32_t)__cvta_generic_to_shared(&sm->B[0][0]);
    int t = threadIdx.x;
#pragma unroll
    for (int p = 0; p < 2; p++) {
        int idx = t + p * 256;
        int row = idx >> 2, seg = idx & 3;
        uint32_t soff = (uint32_t)(row * SPAD + seg * 8) * 2;
        int grow = row0 + row;
        int pred = (grow < N_NODES) ? 16 : 0;
        long aoff = (long)min(grow, N_NODES - 1) * asr + ka + seg * 8;
        cpa16(bA + soff, A + aoff, pred);
        long boff = (long)(coln0 + row) * bsr + kb + seg * 8;
        cpa16(bB + soff, B + boff, 16);
    }
    asm volatile("cp.async.commit_group;");
}

__device__ __forceinline__ void mma_chunk(GemmSmem* sm, float acc[2][8][4],
                                          int wm, int wn, int lane) {
    uint32_t baseA = (uint32_t)__cvta_generic_to_shared(&sm->A[0][0]);
    uint32_t baseB = (uint32_t)__cvta_generic_to_shared(&sm->B[0][0]);
#pragma unroll
    for (int ks = 0; ks < 2; ks++) {
        uint32_t a[2][4];
#pragma unroll
        for (int mi = 0; mi < 2; mi++) {
            int row = wm * 32 + mi * 16 + (lane & 15);
            int col = ks * 16 + ((lane >> 4) << 3);
            uint32_t off = (uint32_t)(row * SPAD + col) * 2;
            ldsm_x4(a[mi][0], a[mi][1], a[mi][2], a[mi][3], baseA + off);
        }
#pragma unroll
        for (int nj = 0; nj < 4; nj++) {
            int row = wn * 64 + nj * 16 + ((lane >> 4) << 3) + (lane & 7);
            int col = ks * 16 + ((lane >> 3) & 1) * 8;
            uint32_t off = (uint32_t)(row * SPAD + col) * 2;
            uint32_t b0, b1, b2, b3;
            ldsm_x4(b0, b1, b2, b3, baseB + off);
#pragma unroll
            for (int mi = 0; mi < 2; mi++) {
                mma_fp16(acc[mi][nj * 2 + 0], a[mi], b0, b1);
                mma_fp16(acc[mi][nj * 2 + 1], a[mi], b2, b3);
            }
        }
    }
}

// h = relu([mean1|x] @ [W1l;W1r] + b1) -> fp16
__global__ __launch_bounds__(256, 2)
void gemm1_tc(const float* __restrict__ b1) {
    extern __shared__ __align__(16) char smraw[];
    GemmSmem* st = (GemmSmem*)smraw;
    float acc[2][8][4];
#pragma unroll
    for (int i = 0; i < 2; i++)
#pragma unroll
        for (int j = 0; j < 8; j++)
#pragma unroll
            for (int k = 0; k < 4; k++) acc[i][j][k] = 0.f;

    int lane = threadIdx.x & 31;
    int wid  = threadIdx.x >> 5;
    int wm = wid & 3, wn = wid >> 2;
    int row0 = blockIdx.x * GBM;
    int col0 = blockIdx.y * GBN;
    const int NC = 16;   // K = 512

    auto issue = [&](int c) {
        int k0 = c * GBK;
        const __half* As;
        int kk;
        if (k0 < 256) { As = g_m1; kk = k0; }
        else          { As = g_xf; kk = k0 - 256; }
        load_chunk(&st[c % NSTAGE], As, row0, kk, D_IN, g_w1, col0, k0, 2 * D_IN);
    };

    issue(0);
    issue(1);
    issue(2);
#pragma unroll 1
    for (int c = 0; c < NC; c++) {
        pipe_wait(c, NC);
        __syncthreads();
        mma_chunk(&st[c % NSTAGE], acc, wm, wn, lane);
        if (c + 3 < NC) issue(c + 3);
    }

    int g = lane >> 2, tg = lane & 3;
#pragma unroll
    for (int mi = 0; mi < 2; mi++) {
        int r = row0 + wm * 32 + mi * 16 + g;
#pragma unroll
        for (int t = 0; t < 8; t++) {
            int c = col0 + wn * 64 + t * 8 + tg * 2;
            float bb0 = b1[c], bb1 = b1[c + 1];
            if (r < N_NODES) {
                float v0 = fmaxf(acc[mi][t][0] + bb0, 0.f);
                float v1 = fmaxf(acc[mi][t][1] + bb1, 0.f);
                *(uint32_t*)(g_hf + (long)r * D_HID + c) =
                    hpack(__float2half(v0), __float2half(v1));
            }
            if (r + 8 < N_NODES) {
                float v0 = fmaxf(acc[mi][t][2] + bb0, 0.f);
                float v1 = fmaxf(acc[mi][t][3] + bb1, 0.f);
                *(uint32_t*)(g_hf + (long)(r + 8) * D_HID + c) =
                    hpack(__float2half(v0), __float2half(v1));
            }
        }
    }
}

// [y2|z2] = h @ [W2l|W2r] (+b2 on z2 half); y2 stored fp16
__global__ __launch_bounds__(256, 2)
void gemm2_tc(const float* __restrict__ b2) {
    extern __shared__ __align__(16) char smraw[];
    GemmSmem* st = (GemmSmem*)smraw;
    float acc[2][8][4];
#pragma unroll
    for (int i = 0; i < 2; i++)
#pragma unroll
        for (int j = 0; j < 8; j++)
#pragma unroll
            for (int k = 0; k < 4; k++) acc[i][j][k] = 0.f;

    int lane = threadIdx.x & 31;
    int wid  = threadIdx.x >> 5;
    int wm = wid & 3, wn = wid >> 2;
    int row0 = blockIdx.x * GBM;
    int col0 = blockIdx.y * GBN;
    const int NC = 8;    // K = 256

    auto issue = [&](int c) {
        int k0 = c * GBK;
        load_chunk(&st[c % NSTAGE], g_hf, row0, k0, D_HID, g_w2, col0, k0, D_HID);
    };

    issue(0);
    issue(1);
    issue(2);
#pragma unroll 1
    for (int c = 0; c < NC; c++) {
        pipe_wait(c, NC);
        __syncthreads();
        mma_chunk(&st[c % NSTAGE], acc, wm, wn, lane);
        if (c + 3 < NC) issue(c + 3);
    }

    int g = lane >> 2, tg = lane & 3;
#pragma unroll
    for (int mi = 0; mi < 2; mi++) {
        int r = row0 + wm * 32 + mi * 16 + g;
#pragma unroll
        for (int t = 0; t < 8; t++) {
            int cg = col0 + wn * 64 + t * 8 + tg * 2;   // 0..255
            bool zside = (cg >= 128);
            int cl = zside ? cg - 128 : cg;
            if (!zside) {
                if (r < N_NODES)
                    *(uint32_t*)(g_y2f + (long)r * D_OUT + cl) =
                        hpack(__float2half(acc[mi][t][0]), __float2half(acc[mi][t][1]));
                if (r + 8 < N_NODES)
                    *(uint32_t*)(g_y2f + (long)(r + 8) * D_OUT + cl) =
                        hpack(__float2half(acc[mi][t][2]), __float2half(acc[mi][t][3]));
            } else {
                float bb0 = b2[cl], bb1 = b2[cl + 1];
                if (r < N_NODES) {
                    float2 o = make_float2(acc[mi][t][0] + bb0, acc[mi][t][1] + bb1);
                    *(float2*)(g_z2 + (long)r * D_OUT + cl) = o;
                }
                if (r + 8 < N_NODES) {
                    float2 o = make_float2(acc[mi][t][2] + bb0, acc[mi][t][3] + bb1);
                    *(float2*)(g_z2 + (long)(r + 8) * D_OUT + cl) = o;
                }
            }
        }
    }
}

// ---- gather2 + final: out = mean(fp16 y2) + z2.  TWO nodes per warp,
// 16 lanes per node, uint4 (16B) per lane => 256B/row, 2x row parallelism.
// Per-column accumulation order identical to the 1-node/warp version.
__device__ __forceinline__ void acc_row8q(float* acc, const uint4& p) {
    float2 f0 = __half22float2(*(const __half2*)&p.x);
    float2 f1 = __half22float2(*(const __half2*)&p.y);
    float2 f2 = __half22float2(*(const __half2*)&p.z);
    float2 f3 = __half22float2(*(const __half2*)&p.w);
    acc[0] += f0.x; acc[1] += f0.y; acc[2] += f1.x; acc[3] += f1.y;
    acc[4] += f2.x; acc[5] += f2.y; acc[6] += f3.x; acc[7] += f3.y;
}

__global__ void gather2_final_kernel(float* __restrict__ out) {
    long tid = blockIdx.x * (long)blockDim.x + threadIdx.x;
    int node   = (int)(tid >> 4);          // 16 threads per node
    int lane16 = (int)(tid & 15);
    if (node >= N_NODES) return;
    int s = g_rowstart[node], e = g_rowstart[node + 1];
    float acc[8];
#pragma unroll
    for (int j = 0; j < 8; j++) acc[j] = 0.f;
    int i = s;
    for (; i + 8 <= e; i += 8) {
        uint4 p[8];
#pragma unroll
        for (int u = 0; u < 8; u++)
            p[u] = ((const uint4*)(g_y2f + (long)g_csr[i + u] * D_OUT))[lane16];
#pragma unroll
        for (int u = 0; u < 8; u++) acc_row8q(acc, p[u]);
    }
    for (; i + 4 <= e; i += 4) {
        uint4 p[4];
#pragma unroll
        for (int u = 0; u < 4; u++)
            p[u] = ((const uint4*)(g_y2f + (long)g_csr[i + u] * D_OUT))[lane16];
#pragma unroll
        for (int u = 0; u < 4; u++) acc_row8q(acc, p[u]);
    }
    for (; i < e; i++) {
        uint4 p = ((const uint4*)(g_y2f + (long)g_csr[i] * D_OUT))[lane16];
        acc_row8q(acc, p);
    }
    float r = 1.0f / fmaxf((float)(e - s), 1.0f);
    const float4* zp = (const float4*)(g_z2 + (long)node * D_OUT) + lane16 * 2;
    float4*       op = (float4*)(out + (long)node * D_OUT) + lane16 * 2;
    float4 z0 = zp[0], z1 = zp[1];
    float4 o0, o1;
    o0.x = acc[0] * r + z0.x;
    o0.y = acc[1] * r + z0.y;
    o0.z = acc[2] * r + z0.z;
    o0.w = acc[3] * r + z0.w;
    o1.x = acc[4] * r + z1.x;
    o1.y = acc[5] * r + z1.y;
    o1.z = acc[6] * r + z1.z;
    o1.w = acc[7] * r + z1.w;
    op[0] = o0;
    op[1] = o1;
}

extern "C" void kernel_launch(void* const* d_in, const int* in_sizes, int n_in,
                              void* d_out, int out_size) {
    const float* x   = (const float*)d_in[0];
    const int*   ei  = (const int*)d_in[1];
    const float* W1l = (const float*)d_in[2];
    const float* b1  = (const float*)d_in[3];
    const float* W1r = (const float*)d_in[4];
    const float* W2l = (const float*)d_in[5];
    const float* b2  = (const float*)d_in[6];
    const float* W2r = (const float*)d_in[7];
    float* out = (float*)d_out;

    static cudaStream_t s_side = nullptr;
    static cudaEvent_t  s_evFork = nullptr, s_evJoin = nullptr;
    if (s_side == nullptr) {
        cudaStreamCreateWithFlags(&s_side, cudaStreamNonBlocking);
        cudaEventCreateWithFlags(&s_evFork, cudaEventDisableTiming);
        cudaEventCreateWithFlags(&s_evJoin, cudaEventDisableTiming);
    }

    cudaFuncSetAttribute(gemm1_tc, cudaFuncAttributeMaxDynamicSharedMemorySize,
                         (int)GEMM_SMEM_BYTES);
    cudaFuncSetAttribute(gemm2_tc, cudaFuncAttributeMaxDynamicSharedMemorySize,
                         (int)GEMM_SMEM_BYTES);

    // Fork: prep on side stream, concurrent with CSR build (disjoint arrays).
    cudaEventRecord(s_evFork, 0);
    cudaStreamWaitEvent(s_side, s_evFork, 0);
    prep_kernel<<<(N_NODES * D_IN / 4 + 255) / 256, 256, 0, s_side>>>(
        x, W1l, W1r, W2l, W2r);
    cudaEventRecord(s_evJoin, s_side);

    zero_deg_kernel<<<(N_NODES + 255) / 256, 256>>>();
    degree_kernel<<<(N_EDGES / 4 + 255) / 256, 256>>>(ei);
    scan_p1_kernel<<<SCAN_NB, SCAN_B>>>();
    scan_p3_kernel<<<SCAN_NB, SCAN_B>>>();
    fill_kernel<<<(N_EDGES / 4 + 255) / 256, 256>>>(ei);

    // Join: gather1 needs g_xf (prep) + CSR (fill).
    cudaStreamWaitEvent(0, s_evJoin, 0);
    gather1_kernel<<<(N_NODES * 32 + 255) / 256, 256>>>();

    gemm1_tc<<<dim3((N_NODES + GBM - 1) / GBM, 2), 256, GEMM_SMEM_BYTES>>>(b1);
    gemm2_tc<<<dim3((N_NODES + GBM - 1) / GBM, 2), 256, GEMM_SMEM_BYTES>>>(b2);

    gather2_final_kernel<<<((long)N_NODES * 16 + 255) / 256, 256>>>(out);
}